// round 1
// baseline (speedup 1.0000x reference)
#include <cuda_runtime.h>
#include <math.h>

#define BB   16
#define HH   512
#define LL   2048
#define NN2  32
#define QQ   64
#define NCH  (LL/QQ)   // 32 chunks
#define PI_F 3.14159265358979323846f

// Scratch (allocation-free rule: device globals)
__device__ float g_y[(size_t)BB*HH*LL];          // gelu(conv + uD), 64 MB
__device__ float g_hid[(size_t)BB*HH*2*HH];      // tanh(y@W1+b1),  32 MB

// ---------------------------------------------------------------------------
// Kernel 1: S4D causal conv via chunked scan + uD + exact GELU
// One block per (b,h) row. 256 threads.
// ---------------------------------------------------------------------------
__global__ __launch_bounds__(256) void conv_kernel(
    const float* __restrict__ u, const float* __restrict__ D,
    const float* __restrict__ log_dt, const float* __restrict__ C_re,
    const float* __restrict__ C_im, float* __restrict__ y_out)
{
    __shared__ float  u_s[LL];                 // 8 KB
    __shared__ float2 ce[NN2][QQ + 1];         // Ceff_n * lam^p (p=0..Q), 16.6 KB
    __shared__ float2 Dc[NCH][NN2];            // chunk sums -> boundary states, 8 KB
    __shared__ float2 Ceff_s[NN2];
    __shared__ float  k_s[QQ];                 // Toeplitz kernel taps

    const int bh  = blockIdx.x;
    const int h   = bh & (HH - 1);
    const int tid = threadIdx.x;

    const float* urow = u + (size_t)bh * LL;
    for (int i = tid; i < LL / 4; i += 256)
        ((float4*)u_s)[i] = ((const float4*)urow)[i];

    const float dt = expf(log_dt[h]);

    // Ceff_n = 2 * (C_re + i C_im) * (exp(dt*A_n) - 1) / A_n  (factor 2 folded in)
    if (tid < NN2) {
        const int n = tid;
        const float are = -0.5f, aim = PI_F * (float)n;
        float s, c; sincosf(aim * dt, &s, &c);
        const float mag = expf(are * dt);
        const float er = mag * c - 1.0f;
        const float ei = mag * s;
        const float den = are * are + aim * aim;
        const float wr = (er * are + ei * aim) / den;
        const float wi = (ei * are - er * aim) / den;
        const float cr = C_re[h * NN2 + n], ci = C_im[h * NN2 + n];
        Ceff_s[n] = make_float2(2.0f * (cr * wr - ci * wi),
                                2.0f * (cr * wi + ci * wr));
    }
    __syncthreads();

    // Fill ce[n][p] = Ceff_n * lam_n^p with directly-computed powers (no drift)
    for (int idx = tid; idx < NN2 * (QQ + 1); idx += 256) {
        const int n = idx / (QQ + 1), p = idx % (QQ + 1);
        float s, c; sincosf(PI_F * (float)n * dt * (float)p, &s, &c);
        const float mag = expf(-0.5f * dt * (float)p);
        const float lr = mag * c, li = mag * s;
        const float2 cf = Ceff_s[n];
        ce[n][p] = make_float2(cf.x * lr - cf.y * li, cf.x * li + cf.y * lr);
    }

    // Horner chunk sums: d_{c,n} = sum_{j=0}^{Q-1} lam^{Q-1-j} u[cQ+j]
    for (int t4 = 0; t4 < 4; t4++) {
        const int task = tid + 256 * t4;
        const int c = task >> 5, n = task & 31;
        float s, cc; sincosf(PI_F * (float)n * dt, &s, &cc);
        const float mag = expf(-0.5f * dt);
        const float lr = mag * cc, li = mag * s;
        float dr = 0.f, di = 0.f;
        const float* up = u_s + c * QQ;
#pragma unroll 8
        for (int j = 0; j < QQ; j++) {
            const float uj = up[j];
            const float nr = dr * lr - di * li + uj;
            di = dr * li + di * lr;
            dr = nr;
        }
        Dc[c][n] = make_float2(dr, di);
    }
    __syncthreads();

    // warp0: sequential prefix over chunks -> Dc[c][n] := S_c (state before chunk c)
    if (tid < 32) {
        const int n = tid;
        float s, c; sincosf(PI_F * (float)n * dt * (float)QQ, &s, &c);
        const float mag = expf(-0.5f * dt * (float)QQ);
        const float lr = mag * c, li = mag * s;
        float sr = 0.f, si = 0.f;
        for (int cc = 0; cc < NCH; cc++) {
            const float2 d = Dc[cc][n];
            Dc[cc][n] = make_float2(sr, si);
            const float nr = sr * lr - si * li + d.x;
            si = sr * li + si * lr + d.y;
            sr = nr;
        }
    } else if (tid >= 64 && tid < 128) {
        // k_s[d] = 2 Re sum_n Ceff_n lam^d  (factor 2 already in Ceff)
        const int d = tid - 64;
        float s = 0.f;
        for (int n = 0; n < NN2; n++) s += ce[n][d].x;
        k_s[d] = s;
    }
    __syncthreads();

    const float Dh = D[h];
    float* yrow = y_out + (size_t)bh * LL;
    for (int it = 0; it < 8; it++) {
        const int l = tid + 256 * it;
        const int c = l >> 6, t = l & 63;
        float acc = Dh * u_s[l];
        const float* up = u_s + c * QQ;
        for (int j = 0; j <= t; j++) acc += k_s[t - j] * up[j];
        float inter = 0.f;
#pragma unroll 8
        for (int n = 0; n < NN2; n++) {
            const float2 cv = ce[n][t + 1];
            const float2 Sv = Dc[c][n];
            inter += cv.x * Sv.x - cv.y * Sv.y;
        }
        acc += inter;
        // exact GELU
        const float g = 0.5f * acc * (1.0f + erff(acc * 0.7071067811865476f));
        yrow[l] = g;
    }
}

// ---------------------------------------------------------------------------
// Kernel 2: fp32 SGEMM 128x128x8, 256 threads, 8x8 microtile.
// C = act(A(MxK,rowmajor) @ B(KxN,rowmajor) + bias), act = tanh if DO_TANH
// M,N multiples of 128; K multiple of 8.
// ---------------------------------------------------------------------------
template <int DO_TANH>
__global__ __launch_bounds__(256) void gemm_kernel(
    const float* __restrict__ A, const float* __restrict__ Bm,
    const float* __restrict__ bias, float* __restrict__ C,
    int M, int N, int K)
{
    __shared__ float As[8][128];
    __shared__ float Bs[8][128];

    const int bm = blockIdx.y * 128;
    const int bn = blockIdx.x * 128;
    const int tid = threadIdx.x;

    const int a_row = tid >> 1;            // 0..127
    const int a_col = (tid & 1) * 4;       // 0 or 4
    const int b_row = tid >> 5;            // 0..7
    const int b_col = (tid & 31) * 4;      // 0..124
    const int tx = tid & 15, ty = tid >> 4;

    float acc[8][8];
#pragma unroll
    for (int i = 0; i < 8; i++)
#pragma unroll
        for (int j = 0; j < 8; j++) acc[i][j] = 0.f;

    const float* Aptr = A + (size_t)(bm + a_row) * K + a_col;
    const float* Bptr = Bm + (size_t)b_row * N + bn + b_col;

    for (int k0 = 0; k0 < K; k0 += 8) {
        const float4 av = *(const float4*)(Aptr + k0);
        As[a_col + 0][a_row] = av.x;
        As[a_col + 1][a_row] = av.y;
        As[a_col + 2][a_row] = av.z;
        As[a_col + 3][a_row] = av.w;
        const float4 bv = *(const float4*)(Bptr + (size_t)k0 * N);
        *(float4*)&Bs[b_row][b_col] = bv;
        __syncthreads();

#pragma unroll
        for (int k = 0; k < 8; k++) {
            float ar[8], br[8];
            *(float4*)&ar[0] = *(const float4*)&As[k][ty * 8];
            *(float4*)&ar[4] = *(const float4*)&As[k][ty * 8 + 4];
            *(float4*)&br[0] = *(const float4*)&Bs[k][tx * 8];
            *(float4*)&br[4] = *(const float4*)&Bs[k][tx * 8 + 4];
#pragma unroll
            for (int i = 0; i < 8; i++)
#pragma unroll
                for (int j = 0; j < 8; j++)
                    acc[i][j] += ar[i] * br[j];
        }
        __syncthreads();
    }

#pragma unroll
    for (int i = 0; i < 8; i++) {
        const int row = bm + ty * 8 + i;
#pragma unroll
        for (int j = 0; j < 8; j++) {
            const int col = bn + tx * 8 + j;
            float v = acc[i][j] + bias[col];
            if (DO_TANH) v = tanhf(v);
            C[(size_t)row * N + col] = v;
        }
    }
}

// ---------------------------------------------------------------------------
extern "C" void kernel_launch(void* const* d_in, const int* in_sizes, int n_in,
                              void* d_out, int out_size)
{
    const float* u      = (const float*)d_in[0];
    const float* D      = (const float*)d_in[1];
    const float* log_dt = (const float*)d_in[2];
    const float* C_re   = (const float*)d_in[3];
    const float* C_im   = (const float*)d_in[4];
    const float* W1     = (const float*)d_in[5];
    const float* b1     = (const float*)d_in[6];
    const float* W2     = (const float*)d_in[7];
    const float* b2     = (const float*)d_in[8];
    float* out = (float*)d_out;

    float *yp, *hp;
    cudaGetSymbolAddress((void**)&yp, g_y);
    cudaGetSymbolAddress((void**)&hp, g_hid);

    const int M = BB * HH;      // 8192
    conv_kernel<<<BB * HH, 256>>>(u, D, log_dt, C_re, C_im, yp);
    gemm_kernel<1><<<dim3((2 * HH) / 128, M / 128), 256>>>(yp, W1, b1, hp, M, 2 * HH, LL);
    gemm_kernel<0><<<dim3(HH / 128, M / 128), 256>>>(hp, W2, b2, out, M, HH, 2 * HH);
}

// round 2
// speedup vs baseline: 1.0003x; 1.0003x over previous
#include <cuda_runtime.h>
#include <math.h>

#define BB   16
#define HH   512
#define LL   2048
#define NN2  32
#define QQ   64
#define NCH  (LL/QQ)   // 32 chunks
#define PI_F 3.14159265358979323846f

// Scratch (allocation-free rule: device globals)
__device__ float g_y[(size_t)BB*HH*LL];          // gelu(conv + uD), 64 MB
__device__ float g_hid[(size_t)BB*HH*2*HH];      // tanh(y@W1+b1),  32 MB

// ---------------------------------------------------------------------------
// Kernel 1: S4D causal conv via chunked scan + uD + exact GELU
// One block per (b,h) row. 256 threads.
// ---------------------------------------------------------------------------
__global__ __launch_bounds__(256) void conv_kernel(
    const float* __restrict__ u, const float* __restrict__ D,
    const float* __restrict__ log_dt, const float* __restrict__ C_re,
    const float* __restrict__ C_im, float* __restrict__ y_out)
{
    __shared__ float  u_s[LL];                 // 8 KB
    __shared__ float2 ce[NN2][QQ + 1];         // Ceff_n * lam^p (p=0..Q), 16.6 KB
    __shared__ float2 Dc[NCH][NN2];            // chunk sums -> boundary states, 8 KB
    __shared__ float2 Ceff_s[NN2];
    __shared__ float  k_s[QQ];                 // Toeplitz kernel taps

    const int bh  = blockIdx.x;
    const int h   = bh & (HH - 1);
    const int tid = threadIdx.x;

    const float* urow = u + (size_t)bh * LL;
    for (int i = tid; i < LL / 4; i += 256)
        ((float4*)u_s)[i] = ((const float4*)urow)[i];

    const float dt = expf(log_dt[h]);

    // Ceff_n = 2 * (C_re + i C_im) * (exp(dt*A_n) - 1) / A_n  (factor 2 folded in)
    if (tid < NN2) {
        const int n = tid;
        const float are = -0.5f, aim = PI_F * (float)n;
        float s, c; sincosf(aim * dt, &s, &c);
        const float mag = expf(are * dt);
        const float er = mag * c - 1.0f;
        const float ei = mag * s;
        const float den = are * are + aim * aim;
        const float wr = (er * are + ei * aim) / den;
        const float wi = (ei * are - er * aim) / den;
        const float cr = C_re[h * NN2 + n], ci = C_im[h * NN2 + n];
        Ceff_s[n] = make_float2(2.0f * (cr * wr - ci * wi),
                                2.0f * (cr * wi + ci * wr));
    }
    __syncthreads();

    // Fill ce[n][p] = Ceff_n * lam_n^p with directly-computed powers (no drift)
    for (int idx = tid; idx < NN2 * (QQ + 1); idx += 256) {
        const int n = idx / (QQ + 1), p = idx % (QQ + 1);
        float s, c; sincosf(PI_F * (float)n * dt * (float)p, &s, &c);
        const float mag = expf(-0.5f * dt * (float)p);
        const float lr = mag * c, li = mag * s;
        const float2 cf = Ceff_s[n];
        ce[n][p] = make_float2(cf.x * lr - cf.y * li, cf.x * li + cf.y * lr);
    }

    // Horner chunk sums: d_{c,n} = sum_{j=0}^{Q-1} lam^{Q-1-j} u[cQ+j]
    for (int t4 = 0; t4 < 4; t4++) {
        const int task = tid + 256 * t4;
        const int c = task >> 5, n = task & 31;
        float s, cc; sincosf(PI_F * (float)n * dt, &s, &cc);
        const float mag = expf(-0.5f * dt);
        const float lr = mag * cc, li = mag * s;
        float dr = 0.f, di = 0.f;
        const float* up = u_s + c * QQ;
#pragma unroll 8
        for (int j = 0; j < QQ; j++) {
            const float uj = up[j];
            const float nr = dr * lr - di * li + uj;
            di = dr * li + di * lr;
            dr = nr;
        }
        Dc[c][n] = make_float2(dr, di);
    }
    __syncthreads();

    // warp0: sequential prefix over chunks -> Dc[c][n] := S_c (state before chunk c)
    if (tid < 32) {
        const int n = tid;
        float s, c; sincosf(PI_F * (float)n * dt * (float)QQ, &s, &c);
        const float mag = expf(-0.5f * dt * (float)QQ);
        const float lr = mag * c, li = mag * s;
        float sr = 0.f, si = 0.f;
        for (int cc = 0; cc < NCH; cc++) {
            const float2 d = Dc[cc][n];
            Dc[cc][n] = make_float2(sr, si);
            const float nr = sr * lr - si * li + d.x;
            si = sr * li + si * lr + d.y;
            sr = nr;
        }
    } else if (tid >= 64 && tid < 128) {
        // k_s[d] = 2 Re sum_n Ceff_n lam^d  (factor 2 already in Ceff)
        const int d = tid - 64;
        float s = 0.f;
        for (int n = 0; n < NN2; n++) s += ce[n][d].x;
        k_s[d] = s;
    }
    __syncthreads();

    const float Dh = D[h];
    float* yrow = y_out + (size_t)bh * LL;
    for (int it = 0; it < 8; it++) {
        const int l = tid + 256 * it;
        const int c = l >> 6, t = l & 63;
        float acc = Dh * u_s[l];
        const float* up = u_s + c * QQ;
        for (int j = 0; j <= t; j++) acc += k_s[t - j] * up[j];
        float inter = 0.f;
#pragma unroll 8
        for (int n = 0; n < NN2; n++) {
            const float2 cv = ce[n][t + 1];
            const float2 Sv = Dc[c][n];
            inter += cv.x * Sv.x - cv.y * Sv.y;
        }
        acc += inter;
        // exact GELU
        const float g = 0.5f * acc * (1.0f + erff(acc * 0.7071067811865476f));
        yrow[l] = g;
    }
}

// ---------------------------------------------------------------------------
// Kernel 2: fp32 SGEMM 128x128x8, 256 threads, 8x8 microtile.
// C = act(A(MxK,rowmajor) @ B(KxN,rowmajor) + bias), act = tanh if DO_TANH
// M,N multiples of 128; K multiple of 8.
// ---------------------------------------------------------------------------
template <int DO_TANH>
__global__ __launch_bounds__(256) void gemm_kernel(
    const float* __restrict__ A, const float* __restrict__ Bm,
    const float* __restrict__ bias, float* __restrict__ C,
    int M, int N, int K)
{
    __shared__ float As[8][128];
    __shared__ float Bs[8][128];

    const int bm = blockIdx.y * 128;
    const int bn = blockIdx.x * 128;
    const int tid = threadIdx.x;

    const int a_row = tid >> 1;            // 0..127
    const int a_col = (tid & 1) * 4;       // 0 or 4
    const int b_row = tid >> 5;            // 0..7
    const int b_col = (tid & 31) * 4;      // 0..124
    const int tx = tid & 15, ty = tid >> 4;

    float acc[8][8];
#pragma unroll
    for (int i = 0; i < 8; i++)
#pragma unroll
        for (int j = 0; j < 8; j++) acc[i][j] = 0.f;

    const float* Aptr = A + (size_t)(bm + a_row) * K + a_col;
    const float* Bptr = Bm + (size_t)b_row * N + bn + b_col;

    for (int k0 = 0; k0 < K; k0 += 8) {
        const float4 av = *(const float4*)(Aptr + k0);
        As[a_col + 0][a_row] = av.x;
        As[a_col + 1][a_row] = av.y;
        As[a_col + 2][a_row] = av.z;
        As[a_col + 3][a_row] = av.w;
        const float4 bv = *(const float4*)(Bptr + (size_t)k0 * N);
        *(float4*)&Bs[b_row][b_col] = bv;
        __syncthreads();

#pragma unroll
        for (int k = 0; k < 8; k++) {
            float ar[8], br[8];
            *(float4*)&ar[0] = *(const float4*)&As[k][ty * 8];
            *(float4*)&ar[4] = *(const float4*)&As[k][ty * 8 + 4];
            *(float4*)&br[0] = *(const float4*)&Bs[k][tx * 8];
            *(float4*)&br[4] = *(const float4*)&Bs[k][tx * 8 + 4];
#pragma unroll
            for (int i = 0; i < 8; i++)
#pragma unroll
                for (int j = 0; j < 8; j++)
                    acc[i][j] += ar[i] * br[j];
        }
        __syncthreads();
    }

#pragma unroll
    for (int i = 0; i < 8; i++) {
        const int row = bm + ty * 8 + i;
#pragma unroll
        for (int j = 0; j < 8; j++) {
            const int col = bn + tx * 8 + j;
            float v = acc[i][j] + bias[col];
            if (DO_TANH) v = tanhf(v);
            C[(size_t)row * N + col] = v;
        }
    }
}

// ---------------------------------------------------------------------------
extern "C" void kernel_launch(void* const* d_in, const int* in_sizes, int n_in,
                              void* d_out, int out_size)
{
    const float* u      = (const float*)d_in[0];
    const float* D      = (const float*)d_in[1];
    const float* log_dt = (const float*)d_in[2];
    const float* C_re   = (const float*)d_in[3];
    const float* C_im   = (const float*)d_in[4];
    const float* W1     = (const float*)d_in[5];
    const float* b1     = (const float*)d_in[6];
    const float* W2     = (const float*)d_in[7];
    const float* b2     = (const float*)d_in[8];
    float* out = (float*)d_out;

    float *yp, *hp;
    cudaGetSymbolAddress((void**)&yp, g_y);
    cudaGetSymbolAddress((void**)&hp, g_hid);

    const int M = BB * HH;      // 8192
    conv_kernel<<<BB * HH, 256>>>(u, D, log_dt, C_re, C_im, yp);
    gemm_kernel<1><<<dim3((2 * HH) / 128, M / 128), 256>>>(yp, W1, b1, hp, M, 2 * HH, LL);
    gemm_kernel<0><<<dim3(HH / 128, M / 128), 256>>>(hp, W2, b2, out, M, HH, 2 * HH);
}